// round 6
// baseline (speedup 1.0000x reference)
#include <cuda_runtime.h>
#include <stdint.h>

// Problem shapes (fixed by the dataset)
#define B 32
#define T 8192
#define D 128
#define P 1024
#define BLOCKS_PER_BATCH 16
#define PHON_PER_BLOCK (P / BLOCKS_PER_BATCH)   // 64
#define THREADS 256

// ---------------------------------------------------------------------------
// Single-wave fused kernel. Grid = 32 * 16 = 512 blocks (<1 wave at 4
// blocks/SM). Each block:
//   1) loads its batch's 1024 durations (int4/thread, registers only),
//   2) block-exclusive-scans via shfl, packs (start<<4 | d) per phoneme
//      into smem,
//   3) its 8 warps loop over 64 phonemes (8 iters x 1 phoneme/warp), each
//      gather fully unrolled over d<=8 with predicated __ldcs LDG.128.
// Scan is paid 512x (vs 4096x before); no wave tail.
// ---------------------------------------------------------------------------
__global__ void __launch_bounds__(THREADS) fused_kernel(
    const float* __restrict__ mel,
    const int*   __restrict__ dur,
    float*       __restrict__ out)
{
    __shared__ int s_seg[P];                 // packed (start<<4 | d)
    __shared__ int s_wsum[THREADS / 32];

    const int b    = blockIdx.x >> 4;        // / BLOCKS_PER_BATCH
    const int blk  = blockIdx.x & 15;
    const int t    = threadIdx.x;
    const int lane = t & 31;
    const int wid  = t >> 5;

    // --- durations: thread t owns elements [4t, 4t+4) ---
    const int4 dv = reinterpret_cast<const int4*>(dur + b * P)[t];
    const int tsum = dv.x + dv.y + dv.z + dv.w;

    // --- warp inclusive scan of per-thread group sums ---
    int x = tsum;
    #pragma unroll
    for (int off = 1; off < 32; off <<= 1) {
        int y = __shfl_up_sync(0xFFFFFFFFu, x, off);
        if (lane >= off) x += y;
    }
    if (lane == 31) s_wsum[wid] = x;
    __syncthreads();

    // --- warp 0 exclusive-scans the 8 warp totals ---
    if (wid == 0) {
        int s  = (lane < THREADS / 32) ? s_wsum[lane] : 0;
        int tt = s;
        #pragma unroll
        for (int off = 1; off < THREADS / 32; off <<= 1) {
            int y = __shfl_up_sync(0xFFFFFFFFu, tt, off);
            if (lane >= off) tt += y;
        }
        if (lane < THREADS / 32) s_wsum[lane] = tt - s;
    }
    __syncthreads();

    // --- pack (start<<4 | d) for this thread's 4 phonemes ---
    {
        int st = s_wsum[wid] + x - tsum;     // exclusive prefix before 4t
        int4* seg4 = reinterpret_cast<int4*>(s_seg) + t;
        int4 pk;
        pk.x = (st << 4) | dv.x;  st += dv.x;
        pk.y = (st << 4) | dv.y;  st += dv.y;
        pk.z = (st << 4) | dv.z;  st += dv.z;
        pk.w = (st << 4) | dv.w;
        *seg4 = pk;
    }
    __syncthreads();

    // --- main loop: 8 iterations, one phoneme per warp per iteration ---
    const int pbase = blk * PHON_PER_BLOCK;
    const float*  melb = mel + (size_t)b * T * D;
    float*        outb = out + ((size_t)b * P + pbase + wid) * D;

    #pragma unroll
    for (int i = 0; i < PHON_PER_BLOCK / 8; ++i) {
        const int p      = pbase + i * 8 + wid;
        const int packed = s_seg[p];
        const int d      = packed & 15;
        const int st     = packed >> 4;

        const float4* __restrict__ base =
            reinterpret_cast<const float4*>(melb + (size_t)st * D) + lane;

        float4 acc = make_float4(0.f, 0.f, 0.f, 0.f);
        #pragma unroll
        for (int f = 0; f < 8; ++f) {
            if (f < d) {
                float4 v = __ldcs(base + f * (D / 4));
                acc.x += v.x; acc.y += v.y; acc.z += v.z; acc.w += v.w;
            }
        }

        const float inv = (d > 0) ? (1.0f / (float)d) : 0.0f;
        acc.x *= inv; acc.y *= inv; acc.z *= inv; acc.w *= inv;

        __stcs(reinterpret_cast<float4*>(outb + (size_t)i * 8 * D) + lane, acc);
    }
}

extern "C" void kernel_launch(void* const* d_in, const int* in_sizes, int n_in,
                              void* d_out, int out_size) {
    const float* mel = (const float*)d_in[0];
    const int*   dur = (const int*)d_in[1];
    float*       out = (float*)d_out;

    fused_kernel<<<B * BLOCKS_PER_BATCH, THREADS>>>(mel, dur, out);
}

// round 7
// speedup vs baseline: 1.1540x; 1.1540x over previous
#include <cuda_runtime.h>
#include <stdint.h>

// Problem shapes (fixed by the dataset)
#define B 32
#define T 8192
#define D 128
#define P 1024
#define WIN 32       // phonemes per block (four per warp)
#define THREADS 256

// ---------------------------------------------------------------------------
// One-wave fused kernel. Grid = 32768/32 = 1024 blocks; __launch_bounds__
// (256, 7) forces 7 blocks/SM residency -> 148*7=1036 >= 1024: ALL blocks in
// one wave, no tail, 56 warps/SM. Each block scans its batch's durations
// once (shfl scan, packed (start<<4|d) into smem); each warp gathers 4
// consecutive phonemes in 2 batches of 2 (16 predicated __ldcs LDG.128 in
// flight per batch).
// ---------------------------------------------------------------------------
__global__ void __launch_bounds__(THREADS, 7) fused_kernel(
    const float* __restrict__ mel,
    const int*   __restrict__ dur,
    float*       __restrict__ out)
{
    __shared__ int s_seg[P];                 // packed (start<<4 | d)
    __shared__ int s_wsum[THREADS / 32];

    const int b    = blockIdx.x >> 5;        // / 32 blocks per batch
    const int blk  = blockIdx.x & 31;
    const int t    = threadIdx.x;
    const int lane = t & 31;
    const int wid  = t >> 5;

    // --- durations: thread t owns elements [4t, 4t+4) ---
    const int4 dv = reinterpret_cast<const int4*>(dur + b * P)[t];
    const int tsum = dv.x + dv.y + dv.z + dv.w;

    // --- warp inclusive scan of per-thread group sums ---
    int x = tsum;
    #pragma unroll
    for (int off = 1; off < 32; off <<= 1) {
        int y = __shfl_up_sync(0xFFFFFFFFu, x, off);
        if (lane >= off) x += y;
    }
    if (lane == 31) s_wsum[wid] = x;
    __syncthreads();

    // --- warp 0 exclusive-scans the 8 warp totals ---
    if (wid == 0) {
        int s  = (lane < THREADS / 32) ? s_wsum[lane] : 0;
        int tt = s;
        #pragma unroll
        for (int off = 1; off < THREADS / 32; off <<= 1) {
            int y = __shfl_up_sync(0xFFFFFFFFu, tt, off);
            if (lane >= off) tt += y;
        }
        if (lane < THREADS / 32) s_wsum[lane] = tt - s;
    }
    __syncthreads();

    // --- pack (start<<4 | d) for this thread's 4 phonemes ---
    {
        int st = s_wsum[wid] + x - tsum;     // exclusive prefix before 4t
        int4 pk;
        pk.x = (st << 4) | dv.x;  st += dv.x;
        pk.y = (st << 4) | dv.y;  st += dv.y;
        pk.z = (st << 4) | dv.z;  st += dv.z;
        pk.w = (st << 4) | dv.w;
        reinterpret_cast<int4*>(s_seg)[t] = pk;
    }
    __syncthreads();

    // --- gather: each warp owns 4 consecutive phonemes, 2 at a time ---
    const int p0 = blk * WIN + wid * 4;      // warp's first phoneme
    const float* melb = mel + (size_t)b * T * D;
    float*       outb = out + ((size_t)b * P + p0) * D;

    // packed entries are int4-aligned since p0 % 4 == 0
    const int4 seg = reinterpret_cast<const int4*>(s_seg)[p0 >> 2];

    #pragma unroll
    for (int half = 0; half < 2; ++half) {
        const int pkA = (half == 0) ? seg.x : seg.z;
        const int pkB = (half == 0) ? seg.y : seg.w;
        const int dA  = pkA & 15,  stA = pkA >> 4;
        const int dB  = pkB & 15,  stB = pkB >> 4;

        const float4* __restrict__ baseA =
            reinterpret_cast<const float4*>(melb + (size_t)stA * D) + lane;
        const float4* __restrict__ baseB =
            reinterpret_cast<const float4*>(melb + (size_t)stB * D) + lane;

        float4 aA = make_float4(0.f, 0.f, 0.f, 0.f);
        float4 aB = make_float4(0.f, 0.f, 0.f, 0.f);
        #pragma unroll
        for (int f = 0; f < 8; ++f) {
            if (f < dA) {
                float4 v = __ldcs(baseA + f * (D / 4));
                aA.x += v.x; aA.y += v.y; aA.z += v.z; aA.w += v.w;
            }
            if (f < dB) {
                float4 v = __ldcs(baseB + f * (D / 4));
                aB.x += v.x; aB.y += v.y; aB.z += v.z; aB.w += v.w;
            }
        }

        const float iA = (dA > 0) ? (1.0f / (float)dA) : 0.0f;
        const float iB = (dB > 0) ? (1.0f / (float)dB) : 0.0f;
        aA.x *= iA; aA.y *= iA; aA.z *= iA; aA.w *= iA;
        aB.x *= iB; aB.y *= iB; aB.z *= iB; aB.w *= iB;

        float4* __restrict__ o =
            reinterpret_cast<float4*>(outb + (size_t)half * 2 * D) + lane;
        __stcs(o, aA);
        __stcs(o + (D / 4), aB);
    }
}

extern "C" void kernel_launch(void* const* d_in, const int* in_sizes, int n_in,
                              void* d_out, int out_size) {
    const float* mel = (const float*)d_in[0];
    const int*   dur = (const int*)d_in[1];
    float*       out = (float*)d_out;

    fused_kernel<<<(B * P) / WIN, THREADS>>>(mel, dur, out);
}